// round 16
// baseline (speedup 1.0000x reference)
#include <cuda_runtime.h>
#include <cuda_bf16.h>
#include <cuda_fp16.h>
#include <math.h>
#include <stdint.h>

#define SEQ     2048
#define BATCH   2
#define HID     2048
#define NHEADS  16
#define HDIM    128
#define TOK     (SEQ*BATCH)     // 4096
#define QKV_N   (3*HID)         // 6144
#define NBH     (BATCH*NHEADS)  // 32

// ---------------- scratch (device globals; no runtime allocs allowed) -------
__device__ float g_cos[SEQ*64];
__device__ float g_sin[SEQ*64];
// GEMM operands: pure fp16, stride HID
__device__ __align__(1024) __half g_Abuf[TOK*HID];
__device__ __align__(1024) __half g_Bq[QKV_N*HID];
__device__ __align__(1024) __half g_Bd[HID*HID];
// attention operands: pure fp16 (written directly by QKV epilogue)
__device__ __align__(16) __half gq_hi[NBH*SEQ*HDIM];
__device__ __align__(16) __half gk_hi[NBH*SEQ*HDIM];
__device__ __align__(16) __half gvt_hi[NBH*HDIM*SEQ];   // [bh][d][s]

// ============================================================================
// PTX helpers (base-target-safe)
// ============================================================================
__device__ __forceinline__ uint32_t smem_u32(const void* p) {
    uint32_t a;
    asm("{ .reg .u64 t; cvta.to.shared.u64 t, %1; cvt.u32.u64 %0, t; }"
        : "=r"(a) : "l"(p));
    return a;
}
__device__ __forceinline__ void cpasync16(uint32_t s, const void* g) {
    asm volatile("cp.async.cg.shared.global [%0], [%1], 16;" :: "r"(s), "l"(g));
}
#define CP_COMMIT() asm volatile("cp.async.commit_group;" ::: "memory")
#define CP_WAIT(n)  asm volatile("cp.async.wait_group %0;" :: "n"(n) : "memory")

__device__ __forceinline__ void ldsm4(uint32_t* r, uint32_t a) {
    asm volatile("ldmatrix.sync.aligned.m8n8.x4.shared.b16 {%0,%1,%2,%3}, [%4];"
        : "=r"(r[0]), "=r"(r[1]), "=r"(r[2]), "=r"(r[3]) : "r"(a));
}
__device__ __forceinline__ void mma16816h(float* c, const uint32_t* a, const uint32_t* b) {
    asm volatile("mma.sync.aligned.m16n8k16.row.col.f32.f16.f16.f32 "
        "{%0,%1,%2,%3}, {%4,%5,%6,%7}, {%8,%9}, {%0,%1,%2,%3};"
        : "+f"(c[0]), "+f"(c[1]), "+f"(c[2]), "+f"(c[3])
        : "r"(a[0]), "r"(a[1]), "r"(a[2]), "r"(a[3]), "r"(b[0]), "r"(b[1]));
}
__device__ __forceinline__ uint32_t pack2h(float a, float b) {
    __half ha = __float2half(a), hb = __float2half(b);
    return (uint32_t)__half_as_ushort(ha) | ((uint32_t)__half_as_ushort(hb) << 16);
}
// per-lane address shaping for paired-B ldsm4: two n-groups x one k16
__device__ __forceinline__ uint32_t bpair_off(int lane, int stride_h) {
    int row = (lane & 7) + ((lane >> 4) << 3);
    int kof = ((lane >> 3) & 1) * 8;
    return (uint32_t)((row * stride_h + kof) * 2);
}

// ============================================================================
// HMMA fp16 GEMM: C[M,N] = A[M,K] * B[N,K]^T, K=2048, fp32 accum.
// CTA tile 128x128x32, 256 thr, warps 4(m) x 2(n), 3-stage ring, paired-B.
// MODE 1: QKV — bias + FUSED RoPE (q,k) / transpose (v), fp16 outputs.
// MODE 2: dense — plain fp32 C store.
// NOTE (MODE 1): each 128-wide n-tile is exactly one part (q/k/v) of one
// head with the full d=0..127 range, enabling in-smem RoPE pair exchange.
// ============================================================================
#define BK 32
#define ASTR 40
#define TILE_B16 (128*ASTR)
#define STAGE_B16 (2*TILE_B16)
#define STAGE_BYTES (STAGE_B16*2)      // 20480
#define GSTAGES 3
#define RING_BYTES (GSTAGES*STAGE_BYTES)         // 61440
#define EPI_BYTES (128*132*4)                     // 67584 staging tile
#define GEMM_SMEM (EPI_BYTES > RING_BYTES ? EPI_BYTES : RING_BYTES)

template<int MODE>
__global__ void __launch_bounds__(256, 2)
hmma_gemm(const __half* __restrict__ Ag, const __half* __restrict__ Bg,
          const float* __restrict__ bias, float* __restrict__ C, int N)
{
    extern __shared__ __align__(16) __half smbuf[];

    const int tid  = threadIdx.x;
    const int lane = tid & 31;
    const int warp = tid >> 5;
    const int wm = warp >> 1;
    const int wn = warp & 1;
    const int m0 = blockIdx.y * 128;
    const int n0 = blockIdx.x * 128;

    const uint32_t smb = smem_u32(smbuf);
    const int cr  = tid >> 2;
    const int ccn = tid & 3;
    const int KT  = HID / BK;          // 64

    auto prefetch = [&](int kt, int slot) {
        uint32_t base = smb + slot * STAGE_BYTES;
#pragma unroll
        for (int h = 0; h < 2; h++) {
            int r = cr + h * 64;
            uint32_t so = (r * ASTR + ccn * 8) * 2;
            cpasync16(base + so,
                      Ag + (size_t)(m0 + r) * HID + kt * BK + ccn * 8);
            cpasync16(base + TILE_B16*2 + so,
                      Bg + (size_t)(n0 + r) * HID + kt * BK + ccn * 8);
        }
    };

    float acc[2][8][4];
#pragma unroll
    for (int i = 0; i < 2; i++)
#pragma unroll
        for (int j = 0; j < 8; j++)
#pragma unroll
            for (int e = 0; e < 4; e++) acc[i][j][e] = 0.0f;

    const int l16 = lane & 15;
    const uint32_t a_off = (((wm * 32 + l16) * ASTR) + ((lane >> 4) * 8)) * 2;
    const uint32_t b_off = (uint32_t)(wn * 64 * ASTR * 2) + bpair_off(lane, ASTR);

    prefetch(0, 0); CP_COMMIT();
    prefetch(1, 1); CP_COMMIT();

    int slot = 0, pslot = 2;
    for (int kt = 0; kt < KT; kt++) {
        CP_WAIT(1);
        __syncthreads();
        int pf = kt + 2;
        if (pf < KT) prefetch(pf, pslot);
        CP_COMMIT();

        uint32_t ab = smb + slot * STAGE_BYTES + a_off;
        uint32_t bb = smb + slot * STAGE_BYTES + TILE_B16*2 + b_off;

#pragma unroll
        for (int k16 = 0; k16 < BK; k16 += 16) {
            uint32_t bfr[8][2];
#pragma unroll
            for (int p = 0; p < 4; p++) {
                uint32_t r4[4];
                ldsm4(r4, bb + (p * 16 * ASTR + k16) * 2);
                bfr[2*p + 0][0] = r4[0]; bfr[2*p + 0][1] = r4[1];
                bfr[2*p + 1][0] = r4[2]; bfr[2*p + 1][1] = r4[3];
            }
#pragma unroll
            for (int mt = 0; mt < 2; mt++) {
                uint32_t afr[4];
                ldsm4(afr, ab + (mt * 16 * ASTR + k16) * 2);
#pragma unroll
                for (int nt = 0; nt < 8; nt++)
                    mma16816h(acc[mt][nt], afr, bfr[nt]);
            }
        }
        if (++slot == 3) slot = 0;
        if (++pslot == 3) pslot = 0;
    }

    const int g  = lane >> 2;
    const int c2 = (lane & 3) * 2;

    if (MODE == 2) {
#pragma unroll
        for (int mt = 0; mt < 2; mt++)
#pragma unroll
            for (int nt = 0; nt < 8; nt++)
#pragma unroll
                for (int i = 0; i < 2; i++)
#pragma unroll
                    for (int j = 0; j < 2; j++) {
                        int m = m0 + wm * 32 + mt * 16 + g + i * 8;
                        int n = n0 + wn * 64 + nt * 8 + c2 + j;
                        C[(size_t)m * N + n] = acc[mt][nt][i * 2 + j];
                    }
        return;
    }

    // ---------------- MODE 1: fused bias + RoPE / V-transpose epilogue -----
    __syncthreads();   // all ring reads retired before smem reuse
    float* st = (float*)smbuf;          // [128][132] staging tile
#pragma unroll
    for (int mt = 0; mt < 2; mt++)
#pragma unroll
        for (int nt = 0; nt < 8; nt++)
#pragma unroll
            for (int i = 0; i < 2; i++)
#pragma unroll
                for (int j = 0; j < 2; j++) {
                    int ml = wm * 32 + mt * 16 + g + i * 8;
                    int nl = wn * 64 + nt * 8 + c2 + j;
                    st[ml * 132 + nl] = acc[mt][nt][i * 2 + j] + bias[n0 + nl];
                }
    __syncthreads();

    const int head = n0 / (3 * HDIM);
    const int part = (n0 % (3 * HDIM)) >> 7;    // 0=q, 1=k, 2=v

    if (part < 2) {
        __half* dst0 = (part == 0) ? gq_hi : gk_hi;
        // thread grid: per iteration, threads cover 2 rows x 128 cols
#pragma unroll 4
        for (int it = 0; it < 64; it++) {
            int idx = tid + it * 256;
            int ml = idx >> 7;
            int d  = idx & 127;
            float x  = st[ml * 132 + d];
            float xp = st[ml * 132 + (d ^ 64)];
            int m = m0 + ml;
            int s = m >> 1, b = m & 1;
            float c  = g_cos[s * 64 + (d & 63)];
            float sn = g_sin[s * 64 + (d & 63)];
            float out = (d < 64) ? (x * c - xp * sn) : (x * c + xp * sn);
            int bh = b * NHEADS + head;
            dst0[((size_t)bh * SEQ + s) * HDIM + d] = __float2half(out);
        }
    } else {
        // V: transpose to gvt_hi[bh][d][s]; thread owns (d, b)
        int d = tid >> 1, b = tid & 1;
        int bh = b * NHEADS + head;
        __half* dst = gvt_hi + ((size_t)bh * HDIM + d) * SEQ + (m0 >> 1);
#pragma unroll
        for (int sl8 = 0; sl8 < 64; sl8 += 8) {
            __half buf[8];
#pragma unroll
            for (int u = 0; u < 8; u++)
                buf[u] = __float2half(st[(2 * (sl8 + u) + b) * 132 + d]);
            *(uint4*)(dst + sl8) = *(uint4*)buf;
        }
    }
}

// ---------------- conversion: flat fp32 -> fp16 -------------------------------
__global__ void conv_hi(const float* __restrict__ src,
                        __half* __restrict__ dst, int n4)
{
    int idx = blockIdx.x * blockDim.x + threadIdx.x;
    if (idx >= n4) return;
    float4 x = ((const float4*)src)[idx];
    __half h[4];
    h[0] = __float2half(x.x); h[1] = __float2half(x.y);
    h[2] = __float2half(x.z); h[3] = __float2half(x.w);
    *(uint2*)(dst + (size_t)idx * 4) = *(uint2*)h;
}

// ---------------- RoPE table --------------------------------------------------
__global__ void rope_table_kernel() {
    __shared__ float invf[64];
    if (threadIdx.x < 64)
        invf[threadIdx.x] = (float)pow(10000.0, -((double)threadIdx.x) / 64.0);
    __syncthreads();
    int idx = blockIdx.x * blockDim.x + threadIdx.x;
    if (idx >= SEQ * 64) return;
    int s = idx >> 6;
    int i = idx & 63;
    float theta = (float)s * invf[i];
    g_cos[idx] = cosf(theta);
    g_sin[idx] = sinf(theta);
}

// ============================================================================
// FA2-style HMMA causal flash attention, pure fp16, paired ldsm4, balanced
// wave pairing (each CTA: heavy qt then light qt; 256 CTAs = one wave).
// ============================================================================
#define BQ 128
#define BT 64
#define NQT (SEQ/BQ)          // 16
#define QSTR 136
#define KSTR 136
#define VSTR 72

#define OFF_QHI 0
#define SZ_Q    (BQ*QSTR*2)
#define OFF_KHI (OFF_QHI + SZ_Q)
#define SZ_K    (BT*KSTR*2)
#define OFF_VHI (OFF_KHI + SZ_K)
#define SZ_V    (HDIM*VSTR*2)
#define ATTN_SMEM (OFF_VHI + SZ_V)     // 70656

__global__ void __launch_bounds__(256, 2) attn_hmma(__half* __restrict__ Aout) {
    extern __shared__ char smem[];
    const uint32_t sb = smem_u32(smem);

    const int tid  = threadIdx.x;
    const int lane = tid & 31;
    const int w    = tid >> 5;
    const int bh = blockIdx.y;

    const int l16 = lane & 15;
    const int g   = lane >> 2;
    const int c2  = (lane & 3) * 2;

    __half* s_qhi = (__half*)(smem + OFF_QHI);

    const __half* Kh = gk_hi + (size_t)bh*SEQ*HDIM;
    const __half* Vh = gvt_hi + (size_t)bh*HDIM*SEQ;

    auto prefetch_k = [&](int k0) {
#pragma unroll
        for (int it = 0; it < 4; it++) {
            int t = tid + it*256;
            int row = t >> 4, cc = t & 15;
            cpasync16(sb + OFF_KHI + (row*KSTR + cc*8)*2,
                      Kh + (size_t)(k0 + row)*HDIM + cc*8);
        }
    };
    auto prefetch_v = [&](int k0) {
#pragma unroll
        for (int it = 0; it < 4; it++) {
            int t = tid + it*256;
            int d = t >> 3, cc = t & 7;
            cpasync16(sb + OFF_VHI + (d*VSTR + cc*8)*2,
                      Vh + (size_t)d*SEQ + k0 + cc*8);
        }
    };

    const uint32_t qhi_b = sb + OFF_QHI + (((w*16 + l16)*QSTR) + (lane>>4)*8)*2;
    const uint32_t khi4  = sb + OFF_KHI + bpair_off(lane, KSTR);
    const uint32_t vhi4  = sb + OFF_VHI + bpair_off(lane, VSTR);

    const float rnorm = 0.088388347648318447f;
    const int b_idx = bh / NHEADS;
    const int h_idx = bh % NHEADS;

#pragma unroll 1
    for (int pass = 0; pass < 2; pass++) {
        const int qt = pass == 0 ? (NQT - 1 - blockIdx.x) : blockIdx.x;
        const int q0 = qt * BQ;
        const int rbase = q0 + w*16 + g;

        __syncthreads();     // prior pass's Q/K/V reads fully retired

        prefetch_k(0); CP_COMMIT();
        prefetch_v(0); CP_COMMIT();

        // Q tile
        {
            const __half* qh = gq_hi + ((size_t)bh*SEQ + q0) * HDIM;
#pragma unroll
            for (int it = 0; it < 8; it++) {
                int t = tid + it*256;
                int row = t >> 4, cc = t & 15;
                *(uint4*)(s_qhi + row*QSTR + cc*8) = *(const uint4*)(qh + row*HDIM + cc*8);
            }
        }

        float m0 = -1e30f, m1 = -1e30f, l0 = 0.0f, l1 = 0.0f;
        float acc[16][4];
#pragma unroll
        for (int nt = 0; nt < 16; nt++)
#pragma unroll
            for (int e = 0; e < 4; e++) acc[nt][e] = 0.0f;

        const int ntiles = 2*qt + 2;
        for (int kt = 0; kt < ntiles; kt++) {
            const int k0 = kt * BT;

            CP_WAIT(1);          // K(kt) resident
            __syncthreads();     // K (and Q) visible

            // ---- S = q*k (paired-K ldsm4) ----
            float sacc[8][4];
#pragma unroll
            for (int nt = 0; nt < 8; nt++)
#pragma unroll
                for (int e = 0; e < 4; e++) sacc[nt][e] = 0.0f;

#pragma unroll
            for (int k16 = 0; k16 < HDIM; k16 += 16) {
                uint32_t bhi[8][2];
#pragma unroll
                for (int p = 0; p < 4; p++) {
                    uint32_t r4[4];
                    ldsm4(r4, khi4 + (p*16*KSTR + k16)*2);
                    bhi[2*p + 0][0] = r4[0]; bhi[2*p + 0][1] = r4[1];
                    bhi[2*p + 1][0] = r4[2]; bhi[2*p + 1][1] = r4[3];
                }
                uint32_t ahi[4];
                ldsm4(ahi, qhi_b + k16*2);
#pragma unroll
                for (int nt = 0; nt < 8; nt++)
                    mma16816h(sacc[nt], ahi, bhi[nt]);
            }
            __syncthreads();     // K(kt) reads retired

            if (kt + 1 < ntiles) prefetch_k(k0 + BT);
            CP_COMMIT();

            // ---- mask + scale + register softmax ----
#pragma unroll
            for (int nt = 0; nt < 8; nt++) {
#pragma unroll
                for (int e = 0; e < 4; e++) {
                    int r = rbase + (e >> 1)*8;
                    int c = k0 + nt*8 + c2 + (e & 1);
                    float v = sacc[nt][e] * rnorm;
                    if (c > r) v = -10000.0f;
                    sacc[nt][e] = v;
                }
            }
            float mx0 = -1e30f, mx1 = -1e30f;
#pragma unroll
            for (int nt = 0; nt < 8; nt++) {
                mx0 = fmaxf(mx0, fmaxf(sacc[nt][0], sacc[nt][1]));
                mx1 = fmaxf(mx1, fmaxf(sacc[nt][2], sacc[nt][3]));
            }
            mx0 = fmaxf(mx0, __shfl_xor_sync(0xFFFFFFFFu, mx0, 1));
            mx0 = fmaxf(mx0, __shfl_xor_sync(0xFFFFFFFFu, mx0, 2));
            mx1 = fmaxf(mx1, __shfl_xor_sync(0xFFFFFFFFu, mx1, 1));
            mx1 = fmaxf(mx1, __shfl_xor_sync(0xFFFFFFFFu, mx1, 2));
            float mn0 = fmaxf(m0, mx0), mn1 = fmaxf(m1, mx1);
            float scl0 = __expf(m0 - mn0), scl1 = __expf(m1 - mn1);
            m0 = mn0; m1 = mn1;
            float sum0 = 0.0f, sum1 = 0.0f;
#pragma unroll
            for (int nt = 0; nt < 8; nt++) {
                float p0 = __expf(sacc[nt][0] - m0);
                float p1 = __expf(sacc[nt][1] - m0);
                float p2 = __expf(sacc[nt][2] - m1);
                float p3 = __expf(sacc[nt][3] - m1);
                sacc[nt][0] = p0; sacc[nt][1] = p1;
                sacc[nt][2] = p2; sacc[nt][3] = p3;
                sum0 += p0 + p1; sum1 += p2 + p3;
            }
            l0 = l0 * scl0 + sum0;
            l1 = l1 * scl1 + sum1;
#pragma unroll
            for (int nt = 0; nt < 16; nt++) {
                acc[nt][0] *= scl0; acc[nt][1] *= scl0;
                acc[nt][2] *= scl1; acc[nt][3] *= scl1;
            }

            CP_WAIT(1);          // V(kt) resident
            __syncthreads();     // V visible

            // ---- O += p*v (paired-V ldsm4, P packed from registers) ----
#pragma unroll
            for (int s = 0; s < 4; s++) {
                uint32_t aph[4];
                aph[0] = pack2h(sacc[2*s][0],   sacc[2*s][1]);
                aph[1] = pack2h(sacc[2*s][2],   sacc[2*s][3]);
                aph[2] = pack2h(sacc[2*s+1][0], sacc[2*s+1][1]);
                aph[3] = pack2h(sacc[2*s+1][2], sacc[2*s+1][3]);
#pragma unroll
                for (int p = 0; p < 8; p++) {
                    uint32_t r4[4];
                    ldsm4(r4, vhi4 + (p*16*VSTR + s*16)*2);
                    uint32_t bv0[2] = {r4[0], r4[1]};
                    uint32_t bv1[2] = {r4[2], r4[3]};
                    mma16816h(acc[2*p + 0], aph, bv0);
                    mma16816h(acc[2*p + 1], aph, bv1);
                }
            }
            __syncthreads();     // V(kt) reads retired

            if (kt + 1 < ntiles) prefetch_v(k0 + BT);
            CP_COMMIT();
        }

        // ---- finalize: quad-reduce l, divide, write fp16 dense A ----
        l0 += __shfl_xor_sync(0xFFFFFFFFu, l0, 1);
        l0 += __shfl_xor_sync(0xFFFFFFFFu, l0, 2);
        l1 += __shfl_xor_sync(0xFFFFFFFFu, l1, 1);
        l1 += __shfl_xor_sync(0xFFFFFFFFu, l1, 2);
        const float linv0 = 1.0f / l0, linv1 = 1.0f / l1;
#pragma unroll
        for (int i = 0; i < 2; i++) {
            int r = rbase + i*8;
            float linv = i ? linv1 : linv0;
            size_t tok = (size_t)(r*BATCH + b_idx);
            __half* dst = Aout + tok*HID + h_idx*HDIM;
#pragma unroll
            for (int nt = 0; nt < 16; nt++) {
#pragma unroll
                for (int j = 0; j < 2; j++) {
                    float v = acc[nt][i*2 + j] * linv;
                    dst[nt*8 + c2 + j] = __float2half(v);
                }
            }
        }
    }
}

// ---------------- tail bias ---------------------------------------------------
__global__ void tail_copy(const float* __restrict__ src, float* __restrict__ dst, int n) {
    int i = blockIdx.x * blockDim.x + threadIdx.x;
    if (i < n) dst[i] = src[i];
}

// ---------------- launch -------------------------------------------------------
extern "C" void kernel_launch(void* const* d_in, const int* in_sizes, int n_in,
                              void* d_out, int out_size)
{
    const float* hidden  = (const float*)d_in[0];
    const float* w_qkv   = (const float*)d_in[2];
    const float* b_qkv   = (const float*)d_in[3];
    const float* w_dense = (const float*)d_in[4];
    const float* b_dense = (const float*)d_in[5];
    float* out = (float*)d_out;

    void *pA, *pBq, *pBd;
    cudaGetSymbolAddress(&pA,   g_Abuf);
    cudaGetSymbolAddress(&pBq,  g_Bq);
    cudaGetSymbolAddress(&pBd,  g_Bd);

    cudaFuncSetAttribute(hmma_gemm<1>, cudaFuncAttributeMaxDynamicSharedMemorySize, GEMM_SMEM);
    cudaFuncSetAttribute(hmma_gemm<2>, cudaFuncAttributeMaxDynamicSharedMemorySize, GEMM_SMEM);
    cudaFuncSetAttribute(attn_hmma, cudaFuncAttributeMaxDynamicSharedMemorySize, ATTN_SMEM);

    // 0) RoPE table (consumed by QKV epilogue)
    rope_table_kernel<<<(SEQ*64 + 255)/256, 256>>>();

    // 1) convert A (hidden) and B (w_qkv) to fp16
    conv_hi<<<(TOK*HID/4 + 255)/256, 256>>>(hidden, (__half*)pA, TOK*HID/4);
    conv_hi<<<(QKV_N*HID/4 + 255)/256, 256>>>(w_qkv, (__half*)pBq, QKV_N*HID/4);

    // 2) QKV projection with FUSED bias+RoPE (q,k) and V-transpose epilogue
    hmma_gemm<1><<<dim3(QKV_N/128, TOK/128), 256, GEMM_SMEM>>>(
        (const __half*)pA, (const __half*)pBq, b_qkv, nullptr, QKV_N);

    // 3) causal attention (pure fp16, paired q-tiles: one balanced wave)
    attn_hmma<<<dim3(NQT/2, NBH), 256, ATTN_SMEM>>>((__half*)pA);

    // 4) w_dense -> fp16, dense GEMM
    conv_hi<<<(HID*HID/4 + 255)/256, 256>>>(w_dense, (__half*)pBd, HID*HID/4);
    hmma_gemm<2><<<dim3(HID/128, TOK/128), 256, GEMM_SMEM>>>(
        (const __half*)pA, (const __half*)pBd, nullptr, out, HID);

    // 5) bias tail if harness flattens the (output, bias) tuple
    int extra = out_size - TOK*HID;
    if (extra > 0)
        tail_copy<<<(extra + 255)/256, 256>>>(b_dense, out + (size_t)TOK*HID, extra);
    (void)in_sizes; (void)n_in;
}

// round 17
// speedup vs baseline: 1.0338x; 1.0338x over previous
#include <cuda_runtime.h>
#include <cuda_bf16.h>
#include <cuda_fp16.h>
#include <math.h>
#include <stdint.h>

#define SEQ     2048
#define BATCH   2
#define HID     2048
#define NHEADS  16
#define HDIM    128
#define TOK     (SEQ*BATCH)     // 4096
#define QKV_N   (3*HID)         // 6144
#define NBH     (BATCH*NHEADS)  // 32

// ---------------- scratch (device globals; no runtime allocs allowed) -------
__device__ float g_cos[SEQ*64];
__device__ float g_sin[SEQ*64];
// GEMM operands: pure fp16, stride HID
__device__ __align__(1024) __half g_Abuf[TOK*HID];
__device__ __align__(1024) __half g_Bq[QKV_N*HID];
__device__ __align__(1024) __half g_Bd[HID*HID];
// attention operands: pure fp16 (written directly by QKV epilogue)
__device__ __align__(16) __half gq_hi[NBH*SEQ*HDIM];
__device__ __align__(16) __half gk_hi[NBH*SEQ*HDIM];
__device__ __align__(16) __half gvt_hi[NBH*HDIM*SEQ];   // [bh][d][s]

// ============================================================================
// PTX helpers (base-target-safe)
// ============================================================================
__device__ __forceinline__ uint32_t smem_u32(const void* p) {
    uint32_t a;
    asm("{ .reg .u64 t; cvta.to.shared.u64 t, %1; cvt.u32.u64 %0, t; }"
        : "=r"(a) : "l"(p));
    return a;
}
__device__ __forceinline__ void cpasync16(uint32_t s, const void* g) {
    asm volatile("cp.async.cg.shared.global [%0], [%1], 16;" :: "r"(s), "l"(g));
}
#define CP_COMMIT() asm volatile("cp.async.commit_group;" ::: "memory")
#define CP_WAIT(n)  asm volatile("cp.async.wait_group %0;" :: "n"(n) : "memory")

__device__ __forceinline__ void ldsm4(uint32_t* r, uint32_t a) {
    asm volatile("ldmatrix.sync.aligned.m8n8.x4.shared.b16 {%0,%1,%2,%3}, [%4];"
        : "=r"(r[0]), "=r"(r[1]), "=r"(r[2]), "=r"(r[3]) : "r"(a));
}
__device__ __forceinline__ void mma16816h(float* c, const uint32_t* a, const uint32_t* b) {
    asm volatile("mma.sync.aligned.m16n8k16.row.col.f32.f16.f16.f32 "
        "{%0,%1,%2,%3}, {%4,%5,%6,%7}, {%8,%9}, {%0,%1,%2,%3};"
        : "+f"(c[0]), "+f"(c[1]), "+f"(c[2]), "+f"(c[3])
        : "r"(a[0]), "r"(a[1]), "r"(a[2]), "r"(a[3]), "r"(b[0]), "r"(b[1]));
}
__device__ __forceinline__ uint32_t pack2h(float a, float b) {
    __half ha = __float2half(a), hb = __float2half(b);
    return (uint32_t)__half_as_ushort(ha) | ((uint32_t)__half_as_ushort(hb) << 16);
}
// per-lane address shaping for paired-B ldsm4: two n-groups x one k16
__device__ __forceinline__ uint32_t bpair_off(int lane, int stride_h) {
    int row = (lane & 7) + ((lane >> 4) << 3);
    int kof = ((lane >> 3) & 1) * 8;
    return (uint32_t)((row * stride_h + kof) * 2);
}

// ============================================================================
// HMMA fp16 GEMM: C[M,N] = A[M,K] * B[N,K]^T, K=2048, fp32 accum.
// CTA tile 128x128x64 (BK=64 -> 32 barriers), 256 thr, warps 4(m) x 2(n),
// 3-stage ring, paired-B ldsm4.
// MODE 1: QKV — bias + FUSED RoPE (q,k) / transpose (v), fp16 outputs.
// MODE 2: dense — plain fp32 C store.
// ============================================================================
#define BK 64
#define ASTR 72
#define TILE_B16 (128*ASTR)            // 9216 halfs per tile
#define STAGE_B16 (2*TILE_B16)         // A + B
#define STAGE_BYTES (STAGE_B16*2)      // 36864
#define GSTAGES 3
#define RING_BYTES (GSTAGES*STAGE_BYTES)          // 110592
#define EPI_BYTES (128*132*4)                      // 67584 staging tile
#define GEMM_SMEM (EPI_BYTES > RING_BYTES ? EPI_BYTES : RING_BYTES)

template<int MODE>
__global__ void __launch_bounds__(256, 2)
hmma_gemm(const __half* __restrict__ Ag, const __half* __restrict__ Bg,
          const float* __restrict__ bias, float* __restrict__ C, int N)
{
    extern __shared__ __align__(16) __half smbuf[];

    const int tid  = threadIdx.x;
    const int lane = tid & 31;
    const int warp = tid >> 5;
    const int wm = warp >> 1;
    const int wn = warp & 1;
    const int m0 = blockIdx.y * 128;
    const int n0 = blockIdx.x * 128;

    const uint32_t smb = smem_u32(smbuf);
    const int cr  = tid >> 3;          // row 0..31 (x4 groups)
    const int ccn = tid & 7;           // 16B chunk within 128B row
    const int KT  = HID / BK;          // 32

    auto prefetch = [&](int kt, int slot) {
        uint32_t base = smb + slot * STAGE_BYTES;
#pragma unroll
        for (int h = 0; h < 4; h++) {
            int r = cr + h * 32;
            uint32_t so = (r * ASTR + ccn * 8) * 2;
            cpasync16(base + so,
                      Ag + (size_t)(m0 + r) * HID + kt * BK + ccn * 8);
            cpasync16(base + TILE_B16*2 + so,
                      Bg + (size_t)(n0 + r) * HID + kt * BK + ccn * 8);
        }
    };

    float acc[2][8][4];
#pragma unroll
    for (int i = 0; i < 2; i++)
#pragma unroll
        for (int j = 0; j < 8; j++)
#pragma unroll
            for (int e = 0; e < 4; e++) acc[i][j][e] = 0.0f;

    const int l16 = lane & 15;
    const uint32_t a_off = (((wm * 32 + l16) * ASTR) + ((lane >> 4) * 8)) * 2;
    const uint32_t b_off = (uint32_t)(wn * 64 * ASTR * 2) + bpair_off(lane, ASTR);

    prefetch(0, 0); CP_COMMIT();
    prefetch(1, 1); CP_COMMIT();

    int slot = 0, pslot = 2;
    for (int kt = 0; kt < KT; kt++) {
        CP_WAIT(1);
        __syncthreads();
        int pf = kt + 2;
        if (pf < KT) prefetch(pf, pslot);
        CP_COMMIT();

        uint32_t ab = smb + slot * STAGE_BYTES + a_off;
        uint32_t bb = smb + slot * STAGE_BYTES + TILE_B16*2 + b_off;

#pragma unroll
        for (int k16 = 0; k16 < BK; k16 += 16) {
            uint32_t bfr[8][2];
#pragma unroll
            for (int p = 0; p < 4; p++) {
                uint32_t r4[4];
                ldsm4(r4, bb + (p * 16 * ASTR + k16) * 2);
                bfr[2*p + 0][0] = r4[0]; bfr[2*p + 0][1] = r4[1];
                bfr[2*p + 1][0] = r4[2]; bfr[2*p + 1][1] = r4[3];
            }
#pragma unroll
            for (int mt = 0; mt < 2; mt++) {
                uint32_t afr[4];
                ldsm4(afr, ab + (mt * 16 * ASTR + k16) * 2);
#pragma unroll
                for (int nt = 0; nt < 8; nt++)
                    mma16816h(acc[mt][nt], afr, bfr[nt]);
            }
        }
        if (++slot == 3) slot = 0;
        if (++pslot == 3) pslot = 0;
    }

    const int g  = lane >> 2;
    const int c2 = (lane & 3) * 2;

    if (MODE == 2) {
#pragma unroll
        for (int mt = 0; mt < 2; mt++)
#pragma unroll
            for (int nt = 0; nt < 8; nt++)
#pragma unroll
                for (int i = 0; i < 2; i++)
#pragma unroll
                    for (int j = 0; j < 2; j++) {
                        int m = m0 + wm * 32 + mt * 16 + g + i * 8;
                        int n = n0 + wn * 64 + nt * 8 + c2 + j;
                        C[(size_t)m * N + n] = acc[mt][nt][i * 2 + j];
                    }
        return;
    }

    // ---------------- MODE 1: fused bias + RoPE / V-transpose epilogue -----
    __syncthreads();   // all ring reads retired before smem reuse
    float* st = (float*)smbuf;          // [128][132] staging tile
#pragma unroll
    for (int mt = 0; mt < 2; mt++)
#pragma unroll
        for (int nt = 0; nt < 8; nt++)
#pragma unroll
            for (int i = 0; i < 2; i++)
#pragma unroll
                for (int j = 0; j < 2; j++) {
                    int ml = wm * 32 + mt * 16 + g + i * 8;
                    int nl = wn * 64 + nt * 8 + c2 + j;
                    st[ml * 132 + nl] = acc[mt][nt][i * 2 + j] + bias[n0 + nl];
                }
    __syncthreads();

    const int head = n0 / (3 * HDIM);
    const int part = (n0 % (3 * HDIM)) >> 7;    // 0=q, 1=k, 2=v

    if (part < 2) {
        __half* dst0 = (part == 0) ? gq_hi : gk_hi;
#pragma unroll 4
        for (int it = 0; it < 64; it++) {
            int idx = tid + it * 256;
            int ml = idx >> 7;
            int d  = idx & 127;
            float x  = st[ml * 132 + d];
            float xp = st[ml * 132 + (d ^ 64)];
            int m = m0 + ml;
            int s = m >> 1, b = m & 1;
            float c  = g_cos[s * 64 + (d & 63)];
            float sn = g_sin[s * 64 + (d & 63)];
            float out = (d < 64) ? (x * c - xp * sn) : (x * c + xp * sn);
            int bh = b * NHEADS + head;
            dst0[((size_t)bh * SEQ + s) * HDIM + d] = __float2half(out);
        }
    } else {
        // V: transpose to gvt_hi[bh][d][s]; thread owns (d, b)
        int d = tid >> 1, b = tid & 1;
        int bh = b * NHEADS + head;
        __half* dst = gvt_hi + ((size_t)bh * HDIM + d) * SEQ + (m0 >> 1);
#pragma unroll
        for (int sl8 = 0; sl8 < 64; sl8 += 8) {
            __half buf[8];
#pragma unroll
            for (int u = 0; u < 8; u++)
                buf[u] = __float2half(st[(2 * (sl8 + u) + b) * 132 + d]);
            *(uint4*)(dst + sl8) = *(uint4*)buf;
        }
    }
}

// ---------------- conversion: flat fp32 -> fp16 -------------------------------
__global__ void conv_hi(const float* __restrict__ src,
                        __half* __restrict__ dst, int n4)
{
    int idx = blockIdx.x * blockDim.x + threadIdx.x;
    if (idx >= n4) return;
    float4 x = ((const float4*)src)[idx];
    __half h[4];
    h[0] = __float2half(x.x); h[1] = __float2half(x.y);
    h[2] = __float2half(x.z); h[3] = __float2half(x.w);
    *(uint2*)(dst + (size_t)idx * 4) = *(uint2*)h;
}

// ---------------- RoPE table --------------------------------------------------
__global__ void rope_table_kernel() {
    __shared__ float invf[64];
    if (threadIdx.x < 64)
        invf[threadIdx.x] = (float)pow(10000.0, -((double)threadIdx.x) / 64.0);
    __syncthreads();
    int idx = blockIdx.x * blockDim.x + threadIdx.x;
    if (idx >= SEQ * 64) return;
    int s = idx >> 6;
    int i = idx & 63;
    float theta = (float)s * invf[i];
    g_cos[idx] = cosf(theta);
    g_sin[idx] = sinf(theta);
}

// ============================================================================
// FA2-style HMMA causal flash attention, pure fp16, paired ldsm4, balanced
// wave pairing (each CTA: heavy qt then light qt; 256 CTAs = one wave).
// ============================================================================
#define BQ 128
#define BT 64
#define NQT (SEQ/BQ)          // 16
#define QSTR 136
#define KSTR 136
#define VSTR 72

#define OFF_QHI 0
#define SZ_Q    (BQ*QSTR*2)
#define OFF_KHI (OFF_QHI + SZ_Q)
#define SZ_K    (BT*KSTR*2)
#define OFF_VHI (OFF_KHI + SZ_K)
#define SZ_V    (HDIM*VSTR*2)
#define ATTN_SMEM (OFF_VHI + SZ_V)     // 70656

__global__ void __launch_bounds__(256, 2) attn_hmma(__half* __restrict__ Aout) {
    extern __shared__ char smem[];
    const uint32_t sb = smem_u32(smem);

    const int tid  = threadIdx.x;
    const int lane = tid & 31;
    const int w    = tid >> 5;
    const int bh = blockIdx.y;

    const int l16 = lane & 15;
    const int g   = lane >> 2;
    const int c2  = (lane & 3) * 2;

    __half* s_qhi = (__half*)(smem + OFF_QHI);

    const __half* Kh = gk_hi + (size_t)bh*SEQ*HDIM;
    const __half* Vh = gvt_hi + (size_t)bh*HDIM*SEQ;

    auto prefetch_k = [&](int k0) {
#pragma unroll
        for (int it = 0; it < 4; it++) {
            int t = tid + it*256;
            int row = t >> 4, cc = t & 15;
            cpasync16(sb + OFF_KHI + (row*KSTR + cc*8)*2,
                      Kh + (size_t)(k0 + row)*HDIM + cc*8);
        }
    };
    auto prefetch_v = [&](int k0) {
#pragma unroll
        for (int it = 0; it < 4; it++) {
            int t = tid + it*256;
            int d = t >> 3, cc = t & 7;
            cpasync16(sb + OFF_VHI + (d*VSTR + cc*8)*2,
                      Vh + (size_t)d*SEQ + k0 + cc*8);
        }
    };

    const uint32_t qhi_b = sb + OFF_QHI + (((w*16 + l16)*QSTR) + (lane>>4)*8)*2;
    const uint32_t khi4  = sb + OFF_KHI + bpair_off(lane, KSTR);
    const uint32_t vhi4  = sb + OFF_VHI + bpair_off(lane, VSTR);

    const float rnorm = 0.088388347648318447f;
    const int b_idx = bh / NHEADS;
    const int h_idx = bh % NHEADS;

#pragma unroll 1
    for (int pass = 0; pass < 2; pass++) {
        const int qt = pass == 0 ? (NQT - 1 - blockIdx.x) : blockIdx.x;
        const int q0 = qt * BQ;
        const int rbase = q0 + w*16 + g;

        __syncthreads();     // prior pass's Q/K/V reads fully retired

        prefetch_k(0); CP_COMMIT();
        prefetch_v(0); CP_COMMIT();

        // Q tile
        {
            const __half* qh = gq_hi + ((size_t)bh*SEQ + q0) * HDIM;
#pragma unroll
            for (int it = 0; it < 8; it++) {
                int t = tid + it*256;
                int row = t >> 4, cc = t & 15;
                *(uint4*)(s_qhi + row*QSTR + cc*8) = *(const uint4*)(qh + row*HDIM + cc*8);
            }
        }

        float m0 = -1e30f, m1 = -1e30f, l0 = 0.0f, l1 = 0.0f;
        float acc[16][4];
#pragma unroll
        for (int nt = 0; nt < 16; nt++)
#pragma unroll
            for (int e = 0; e < 4; e++) acc[nt][e] = 0.0f;

        const int ntiles = 2*qt + 2;
        for (int kt = 0; kt < ntiles; kt++) {
            const int k0 = kt * BT;

            CP_WAIT(1);          // K(kt) resident
            __syncthreads();     // K (and Q) visible

            // ---- S = q*k (paired-K ldsm4) ----
            float sacc[8][4];
#pragma unroll
            for (int nt = 0; nt < 8; nt++)
#pragma unroll
                for (int e = 0; e < 4; e++) sacc[nt][e] = 0.0f;

#pragma unroll
            for (int k16 = 0; k16 < HDIM; k16 += 16) {
                uint32_t bhi[8][2];
#pragma unroll
                for (int p = 0; p < 4; p++) {
                    uint32_t r4[4];
                    ldsm4(r4, khi4 + (p*16*KSTR + k16)*2);
                    bhi[2*p + 0][0] = r4[0]; bhi[2*p + 0][1] = r4[1];
                    bhi[2*p + 1][0] = r4[2]; bhi[2*p + 1][1] = r4[3];
                }
                uint32_t ahi[4];
                ldsm4(ahi, qhi_b + k16*2);
#pragma unroll
                for (int nt = 0; nt < 8; nt++)
                    mma16816h(sacc[nt], ahi, bhi[nt]);
            }
            __syncthreads();     // K(kt) reads retired

            if (kt + 1 < ntiles) prefetch_k(k0 + BT);
            CP_COMMIT();

            // ---- mask + scale + register softmax ----
#pragma unroll
            for (int nt = 0; nt < 8; nt++) {
#pragma unroll
                for (int e = 0; e < 4; e++) {
                    int r = rbase + (e >> 1)*8;
                    int c = k0 + nt*8 + c2 + (e & 1);
                    float v = sacc[nt][e] * rnorm;
                    if (c > r) v = -10000.0f;
                    sacc[nt][e] = v;
                }
            }
            float mx0 = -1e30f, mx1 = -1e30f;
#pragma unroll
            for (int nt = 0; nt < 8; nt++) {
                mx0 = fmaxf(mx0, fmaxf(sacc[nt][0], sacc[nt][1]));
                mx1 = fmaxf(mx1, fmaxf(sacc[nt][2], sacc[nt][3]));
            }
            mx0 = fmaxf(mx0, __shfl_xor_sync(0xFFFFFFFFu, mx0, 1));
            mx0 = fmaxf(mx0, __shfl_xor_sync(0xFFFFFFFFu, mx0, 2));
            mx1 = fmaxf(mx1, __shfl_xor_sync(0xFFFFFFFFu, mx1, 1));
            mx1 = fmaxf(mx1, __shfl_xor_sync(0xFFFFFFFFu, mx1, 2));
            float mn0 = fmaxf(m0, mx0), mn1 = fmaxf(m1, mx1);
            float scl0 = __expf(m0 - mn0), scl1 = __expf(m1 - mn1);
            m0 = mn0; m1 = mn1;
            float sum0 = 0.0f, sum1 = 0.0f;
#pragma unroll
            for (int nt = 0; nt < 8; nt++) {
                float p0 = __expf(sacc[nt][0] - m0);
                float p1 = __expf(sacc[nt][1] - m0);
                float p2 = __expf(sacc[nt][2] - m1);
                float p3 = __expf(sacc[nt][3] - m1);
                sacc[nt][0] = p0; sacc[nt][1] = p1;
                sacc[nt][2] = p2; sacc[nt][3] = p3;
                sum0 += p0 + p1; sum1 += p2 + p3;
            }
            l0 = l0 * scl0 + sum0;
            l1 = l1 * scl1 + sum1;
#pragma unroll
            for (int nt = 0; nt < 16; nt++) {
                acc[nt][0] *= scl0; acc[nt][1] *= scl0;
                acc[nt][2] *= scl1; acc[nt][3] *= scl1;
            }

            CP_WAIT(1);          // V(kt) resident
            __syncthreads();     // V visible

            // ---- O += p*v (paired-V ldsm4, P packed from registers) ----
#pragma unroll
            for (int s = 0; s < 4; s++) {
                uint32_t aph[4];
                aph[0] = pack2h(sacc[2*s][0],   sacc[2*s][1]);
                aph[1] = pack2h(sacc[2*s][2],   sacc[2*s][3]);
                aph[2] = pack2h(sacc[2*s+1][0], sacc[2*s+1][1]);
                aph[3] = pack2h(sacc[2*s+1][2], sacc[2*s+1][3]);
#pragma unroll
                for (int p = 0; p < 8; p++) {
                    uint32_t r4[4];
                    ldsm4(r4, vhi4 + (p*16*VSTR + s*16)*2);
                    uint32_t bv0[2] = {r4[0], r4[1]};
                    uint32_t bv1[2] = {r4[2], r4[3]};
                    mma16816h(acc[2*p + 0], aph, bv0);
                    mma16816h(acc[2*p + 1], aph, bv1);
                }
            }
            __syncthreads();     // V(kt) reads retired

            if (kt + 1 < ntiles) prefetch_v(k0 + BT);
            CP_COMMIT();
        }

        // ---- finalize: quad-reduce l, divide, write fp16 dense A ----
        l0 += __shfl_xor_sync(0xFFFFFFFFu, l0, 1);
        l0 += __shfl_xor_sync(0xFFFFFFFFu, l0, 2);
        l1 += __shfl_xor_sync(0xFFFFFFFFu, l1, 1);
        l1 += __shfl_xor_sync(0xFFFFFFFFu, l1, 2);
        const float linv0 = 1.0f / l0, linv1 = 1.0f / l1;
#pragma unroll
        for (int i = 0; i < 2; i++) {
            int r = rbase + i*8;
            float linv = i ? linv1 : linv0;
            size_t tok = (size_t)(r*BATCH + b_idx);
            __half* dst = Aout + tok*HID + h_idx*HDIM;
#pragma unroll
            for (int nt = 0; nt < 16; nt++) {
#pragma unroll
                for (int j = 0; j < 2; j++) {
                    float v = acc[nt][i*2 + j] * linv;
                    dst[nt*8 + c2 + j] = __float2half(v);
                }
            }
        }
    }
}

// ---------------- tail bias ---------------------------------------------------
__global__ void tail_copy(const float* __restrict__ src, float* __restrict__ dst, int n) {
    int i = blockIdx.x * blockDim.x + threadIdx.x;
    if (i < n) dst[i] = src[i];
}

// ---------------- launch -------------------------------------------------------
extern "C" void kernel_launch(void* const* d_in, const int* in_sizes, int n_in,
                              void* d_out, int out_size)
{
    const float* hidden  = (const float*)d_in[0];
    const float* w_qkv   = (const float*)d_in[2];
    const float* b_qkv   = (const float*)d_in[3];
    const float* w_dense = (const float*)d_in[4];
    const float* b_dense = (const float*)d_in[5];
    float* out = (float*)d_out;

    void *pA, *pBq, *pBd;
    cudaGetSymbolAddress(&pA,   g_Abuf);
    cudaGetSymbolAddress(&pBq,  g_Bq);
    cudaGetSymbolAddress(&pBd,  g_Bd);

    cudaFuncSetAttribute(hmma_gemm<1>, cudaFuncAttributeMaxDynamicSharedMemorySize, GEMM_SMEM);
    cudaFuncSetAttribute(hmma_gemm<2>, cudaFuncAttributeMaxDynamicSharedMemorySize, GEMM_SMEM);
    cudaFuncSetAttribute(attn_hmma, cudaFuncAttributeMaxDynamicSharedMemorySize, ATTN_SMEM);

    // 0) RoPE table (consumed by QKV epilogue)
    rope_table_kernel<<<(SEQ*64 + 255)/256, 256>>>();

    // 1) convert A (hidden) and B (w_qkv) to fp16
    conv_hi<<<(TOK*HID/4 + 255)/256, 256>>>(hidden, (__half*)pA, TOK*HID/4);
    conv_hi<<<(QKV_N*HID/4 + 255)/256, 256>>>(w_qkv, (__half*)pBq, QKV_N*HID/4);

    // 2) QKV projection with FUSED bias+RoPE (q,k) and V-transpose epilogue
    hmma_gemm<1><<<dim3(QKV_N/128, TOK/128), 256, GEMM_SMEM>>>(
        (const __half*)pA, (const __half*)pBq, b_qkv, nullptr, QKV_N);

    // 3) causal attention (pure fp16, paired q-tiles: one balanced wave)
    attn_hmma<<<dim3(NQT/2, NBH), 256, ATTN_SMEM>>>((__half*)pA);

    // 4) w_dense -> fp16, dense GEMM
    conv_hi<<<(HID*HID/4 + 255)/256, 256>>>(w_dense, (__half*)pBd, HID*HID/4);
    hmma_gemm<2><<<dim3(HID/128, TOK/128), 256, GEMM_SMEM>>>(
        (const __half*)pA, (const __half*)pBd, nullptr, out, HID);

    // 5) bias tail if harness flattens the (output, bias) tuple
    int extra = out_size - TOK*HID;
    if (extra > 0)
        tail_copy<<<(extra + 255)/256, 256>>>(b_dense, out + (size_t)TOK*HID, extra);
    (void)in_sizes; (void)n_in;
}